// round 6
// baseline (speedup 1.0000x reference)
#include <cuda_runtime.h>
#include <cuda_bf16.h>
#include <cstdint>

#define MTOK 8192
#define HID  2048
#define DEX  4096
#define RK   64
#define K1E  (3*HID)   // 6144
#define K2E  (3*DEX)   // 12288
#define KRE  (3*RK)    // 192
#define SPLITK 4

// ---------------- scratch (device globals) ----------------------------------
__device__ __align__(16) __nv_bfloat16 g_Xe  [(size_t)MTOK * K1E];
__device__ __align__(16) __nv_bfloat16 g_Wgue[(size_t)2*DEX * K1E];
__device__ __align__(16) __nv_bfloat16 g_Ague[(size_t)RK * K1E];
__device__ __align__(16) __nv_bfloat16 g_Bgue[(size_t)2*DEX * KRE];
__device__ __align__(16) __nv_bfloat16 g_Wde [(size_t)HID * K2E];
__device__ __align__(16) __nv_bfloat16 g_Ade [(size_t)RK * K2E];
__device__ __align__(16) __nv_bfloat16 g_Bde [(size_t)HID * KRE];
__device__ __align__(16) float         g_Pk  [(size_t)SPLITK * MTOK * RK];
__device__ __align__(16) __nv_bfloat16 g_T1e [(size_t)MTOK * KRE];
__device__ __align__(16) __nv_bfloat16 g_T2e [(size_t)MTOK * KRE];
__device__ __align__(16) __nv_bfloat16 g_He  [(size_t)MTOK * K2E];

// ---------------- fp32 -> bf16x3 expansion (8 elems/thread) -----------------
template<bool ASIDE>
__global__ void cvt_expand8(const float* __restrict__ in,
                            __nv_bfloat16* __restrict__ out,
                            size_t n8, float scale) {
    size_t i = (size_t)blockIdx.x * blockDim.x + threadIdx.x;
    if (i >= n8) return;
    const float4* p = reinterpret_cast<const float4*>(in) + i * 2;
    float4 v0 = p[0], v1 = p[1];
    float x[8] = {v0.x, v0.y, v0.z, v0.w, v1.x, v1.y, v1.z, v1.w};
    __nv_bfloat16 ob[24];
#pragma unroll
    for (int k = 0; k < 8; k++) {
        float xv = x[k] * scale;
        __nv_bfloat16 hi = __float2bfloat16(xv);
        __nv_bfloat16 lo = __float2bfloat16(xv - __bfloat162float(hi));
        ob[3*k] = hi;
        if (ASIDE) { ob[3*k+1] = lo; ob[3*k+2] = hi; }
        else       { ob[3*k+1] = hi; ob[3*k+2] = lo; }
    }
    uint4* o = reinterpret_cast<uint4*>(out + i * 24);
    const uint4* s = reinterpret_cast<const uint4*>(ob);
    o[0] = s[0]; o[1] = s[1]; o[2] = s[2];
}

// ---------------- splitK reduce + 0.25 scale + A-side expansion -------------
__global__ void reduce_expand(const float* __restrict__ P,
                              __nv_bfloat16* __restrict__ out) {
    size_t idx = (size_t)blockIdx.x * blockDim.x + threadIdx.x;
    if (idx >= (size_t)MTOK * RK) return;
    const size_t S = (size_t)MTOK * RK;
    float s = P[idx] + P[idx + S] + P[idx + 2*S] + P[idx + 3*S];
    s *= 0.25f;                       // LORA_ALPHA / R
    __nv_bfloat16 hi = __float2bfloat16(s);
    __nv_bfloat16 lo = __float2bfloat16(s - __bfloat162float(hi));
    out[3*idx] = hi; out[3*idx+1] = lo; out[3*idx+2] = hi;
}

// ---------------- bf16 TN GEMM (mma.sync) -----------------------------------
// MODE 0: C fp32 [M][N], LoRA K-tail.   MODE 1: fused SwiGLU -> He bf16x3,
// gate/up interleaved B rows, n0 = d-offset.   MODE 2: splitK partial.
#define BM 128
#define BN 128
#define BKK 64
#define STAGES 3
#define NTH 256
#define TILE_BYTES (BM * BKK * 2)              // 16 KB
#define SMEM_BYTES (2 * STAGES * TILE_BYTES)   // 96 KB -> 2 CTAs/SM

template<int MODE>
__device__ __forceinline__ void load_tiles(uint32_t smem_u32, int stage,
                                           const __nv_bfloat16* gA,
                                           const __nv_bfloat16* gB,
                                           int m0, int n0, int N, int Ks,
                                           int kt, int tid) {
#pragma unroll
    for (int i = 0; i < 4; i++) {
        int c = tid + i * NTH;
        int row = c >> 3;
        int col = c & 7;
        uint32_t sw = (uint32_t)(col ^ (row & 7)) << 4;
        uint32_t da = smem_u32 + (uint32_t)stage * TILE_BYTES + row * 128 + sw;
        const void* sa = (const void*)(gA + (size_t)(m0 + row) * Ks
                                          + (size_t)kt * BKK + col * 8);
        asm volatile("cp.async.cg.shared.global [%0], [%1], 16;"
                     :: "r"(da), "l"(sa));
        int brow;
        if (MODE == 1) {
            brow = (row & 1) ? (DEX + n0 + (row >> 1)) : (n0 + (row >> 1));
        } else {
            brow = n0 + row; brow = brow < N ? brow : N - 1;  // clamp (N=64)
        }
        uint32_t db = smem_u32 + (uint32_t)(STAGES + stage) * TILE_BYTES
                               + row * 128 + sw;
        const void* sb = (const void*)(gB + (size_t)brow * Ks
                                          + (size_t)kt * BKK + col * 8);
        asm volatile("cp.async.cg.shared.global [%0], [%1], 16;"
                     :: "r"(db), "l"(sb));
    }
}

template<int MODE>
__global__ __launch_bounds__(NTH, 2) void gemm_bf16x3(
    const __nv_bfloat16* __restrict__ A,  const __nv_bfloat16* __restrict__ B,
    const __nv_bfloat16* __restrict__ A2, const __nv_bfloat16* __restrict__ B2,
    void* __restrict__ Cout, int N, int K, int Kt) {
    extern __shared__ char smem[];
    const uint32_t smem_u32 = (uint32_t)__cvta_generic_to_shared(smem);
    const int tid  = threadIdx.x;
    const int warp = tid >> 5, lane = tid & 31;
    const int wm = warp >> 2, wn = warp & 3;
    const int gid = lane >> 2, tig = lane & 3;

    // grouped CTA swizzle (8 y-tiles per x step) for L2 reuse of B panels
    int bx = blockIdx.x, by = blockIdx.y;
    if (MODE != 2 && gridDim.x > 1) {
        const int GRP = 8;
        int lin = by * gridDim.x + bx;
        int per = gridDim.x * GRP;
        int g   = lin / per, rem = lin % per;
        int gy  = g * GRP;
        int h   = gridDim.y - gy; if (h > GRP) h = GRP;
        by = gy + rem % h;
        bx = rem / h;
    }
    const int m0 = by * BM;
    const int n0 = bx * ((MODE == 1) ? 64 : BN);

    float acc[4][4][4];
#pragma unroll
    for (int a = 0; a < 4; a++)
#pragma unroll
        for (int b = 0; b < 4; b++)
#pragma unroll
            for (int c = 0; c < 4; c++) acc[a][b][c] = 0.0f;

    const int a_row_in = (lane & 15);
    const int a_ch_in  = (lane >> 4);
    const int b_row_in = ((lane >> 4) << 3) + (lane & 7);
    const int b_ch_in  = ((lane >> 3) & 1);

    const int cps   = (MODE == 2) ? (K / BKK) / SPLITK : 0;
    const int koff  = (MODE == 2) ? blockIdx.z * cps : 0;
    const int nseg  = (MODE == 2) ? 1 : 2;

    for (int seg = 0; seg < nseg; seg++) {
        const __nv_bfloat16* gA = seg ? A2 : A;
        const __nv_bfloat16* gB = seg ? B2 : B;
        const int Ks = seg ? Kt : K;
        if (Ks == 0) break;
        const int ktiles = (MODE == 2) ? cps : Ks / BKK;

        for (int p = 0; p < STAGES - 1; p++) {
            if (p < ktiles)
                load_tiles<MODE>(smem_u32, p, gA, gB, m0, n0, N, Ks,
                                 koff + p, tid);
            asm volatile("cp.async.commit_group;");
        }

        for (int kt = 0; kt < ktiles; kt++) {
            asm volatile("cp.async.wait_group %0;" :: "n"(STAGES - 2));
            __syncthreads();
            int nk = kt + STAGES - 1;
            if (nk < ktiles)
                load_tiles<MODE>(smem_u32, nk % STAGES, gA, gB, m0, n0, N, Ks,
                                 koff + nk, tid);
            asm volatile("cp.async.commit_group;");

            const int st = kt % STAGES;
            const uint32_t sA = smem_u32 + (uint32_t)st * TILE_BYTES;
            const uint32_t sB = smem_u32 + (uint32_t)(STAGES + st) * TILE_BYTES;

            // double-buffered fragments: prefetch kk+1 while issuing kk's MMAs
            uint32_t ra[2][4][4], rb[2][4][2];
            auto load_frags = [&](int kk, int buf) {
#pragma unroll
                for (int mi = 0; mi < 4; mi++) {
                    int row = wm * 64 + mi * 16 + a_row_in;
                    int ch  = (kk >> 3) + a_ch_in;
                    uint32_t ad = sA + row * 128 + ((uint32_t)(ch ^ (row & 7)) << 4);
                    asm volatile(
                        "ldmatrix.sync.aligned.m8n8.x4.shared.b16 {%0,%1,%2,%3}, [%4];"
                        : "=r"(ra[buf][mi][0]), "=r"(ra[buf][mi][1]),
                          "=r"(ra[buf][mi][2]), "=r"(ra[buf][mi][3])
                        : "r"(ad));
                }
#pragma unroll
                for (int p = 0; p < 2; p++) {
                    int row = wn * 32 + p * 16 + b_row_in;
                    int ch  = (kk >> 3) + b_ch_in;
                    uint32_t bd = sB + row * 128 + ((uint32_t)(ch ^ (row & 7)) << 4);
                    asm volatile(
                        "ldmatrix.sync.aligned.m8n8.x4.shared.b16 {%0,%1,%2,%3}, [%4];"
                        : "=r"(rb[buf][2*p][0]), "=r"(rb[buf][2*p][1]),
                          "=r"(rb[buf][2*p+1][0]), "=r"(rb[buf][2*p+1][1])
                        : "r"(bd));
                }
            };

            load_frags(0, 0);
#pragma unroll
            for (int j = 0; j < 4; j++) {
                const int cur = j & 1;
                if (j < 3) load_frags((j + 1) * 16, cur ^ 1);
#pragma unroll
                for (int mi = 0; mi < 4; mi++)
#pragma unroll
                    for (int ni = 0; ni < 4; ni++)
                        asm volatile(
                            "mma.sync.aligned.m16n8k16.row.col.f32.bf16.bf16.f32 "
                            "{%0,%1,%2,%3}, {%4,%5,%6,%7}, {%8,%9}, {%0,%1,%2,%3};"
                            : "+f"(acc[mi][ni][0]), "+f"(acc[mi][ni][1]),
                              "+f"(acc[mi][ni][2]), "+f"(acc[mi][ni][3])
                            : "r"(ra[cur][mi][0]), "r"(ra[cur][mi][1]),
                              "r"(ra[cur][mi][2]), "r"(ra[cur][mi][3]),
                              "r"(rb[cur][ni][0]), "r"(rb[cur][ni][1]));
            }
        }
        asm volatile("cp.async.wait_group 0;");
        __syncthreads();
    }

    if (MODE == 0) {
        float* C = (float*)Cout;
#pragma unroll
        for (int mi = 0; mi < 4; mi++) {
            int r0 = m0 + wm * 64 + mi * 16 + gid;
#pragma unroll
            for (int ni = 0; ni < 4; ni++) {
                int c0 = n0 + wn * 32 + ni * 8 + tig * 2;
                float2 v0 = make_float2(acc[mi][ni][0], acc[mi][ni][1]);
                float2 v1 = make_float2(acc[mi][ni][2], acc[mi][ni][3]);
                *reinterpret_cast<float2*>(C + (size_t)r0 * N + c0) = v0;
                *reinterpret_cast<float2*>(C + (size_t)(r0 + 8) * N + c0) = v1;
            }
        }
    } else if (MODE == 2) {
        float* C = (float*)Cout + (size_t)blockIdx.z * MTOK * RK;
#pragma unroll
        for (int mi = 0; mi < 4; mi++) {
            int r0 = m0 + wm * 64 + mi * 16 + gid;
#pragma unroll
            for (int ni = 0; ni < 4; ni++) {
                int c0 = wn * 32 + ni * 8 + tig * 2;
                if (c0 < RK) {
                    float2 v0 = make_float2(acc[mi][ni][0], acc[mi][ni][1]);
                    float2 v1 = make_float2(acc[mi][ni][2], acc[mi][ni][3]);
                    *reinterpret_cast<float2*>(C + (size_t)r0 * RK + c0) = v0;
                    *reinterpret_cast<float2*>(C + (size_t)(r0 + 8) * RK + c0) = v1;
                }
            }
        }
    } else {
        // MODE 1: acc pair (c0,c1) = (gate,up), local d = wn*16+ni*4+tig
        float* hs = reinterpret_cast<float*>(smem);   // [128][68] padded
#pragma unroll
        for (int mi = 0; mi < 4; mi++) {
            int rl = wm * 64 + mi * 16 + gid;
#pragma unroll
            for (int ni = 0; ni < 4; ni++) {
                int dl = wn * 16 + ni * 4 + tig;
                float g0 = acc[mi][ni][0], u0 = acc[mi][ni][1];
                hs[rl * 68 + dl]       = u0 * g0 / (1.0f + __expf(-g0));
                float g1 = acc[mi][ni][2], u1 = acc[mi][ni][3];
                hs[(rl + 8) * 68 + dl] = u1 * g1 / (1.0f + __expf(-g1));
            }
        }
        __syncthreads();
        __nv_bfloat16* He = (__nv_bfloat16*)Cout;
#pragma unroll
        for (int it = 0; it < 4; it++) {
            int rl  = it * 32 + (tid >> 3);
            int blk = tid & 7;
            float4 v0 = *reinterpret_cast<float4*>(&hs[rl * 68 + blk * 8]);
            float4 v1 = *reinterpret_cast<float4*>(&hs[rl * 68 + blk * 8 + 4]);
            float x[8] = {v0.x, v0.y, v0.z, v0.w, v1.x, v1.y, v1.z, v1.w};
            __nv_bfloat16 ob[24];
#pragma unroll
            for (int k = 0; k < 8; k++) {
                __nv_bfloat16 hi = __float2bfloat16(x[k]);
                __nv_bfloat16 lo = __float2bfloat16(x[k] - __bfloat162float(hi));
                ob[3*k] = hi; ob[3*k+1] = lo; ob[3*k+2] = hi;
            }
            uint4* o = reinterpret_cast<uint4*>(
                He + (size_t)(m0 + rl) * K2E + 3 * (n0 + blk * 8));
            const uint4* s = reinterpret_cast<const uint4*>(ob);
            o[0] = s[0]; o[1] = s[1]; o[2] = s[2];
        }
    }
}

// ---------------- launcher ---------------------------------------------------
extern "C" void kernel_launch(void* const* d_in, const int* in_sizes, int n_in,
                              void* d_out, int out_size) {
    const float* X   = (const float*)d_in[0];
    const float* Wgu = (const float*)d_in[1];
    const float* Agu = (const float*)d_in[2];
    const float* Bgu = (const float*)d_in[3];
    const float* Wd  = (const float*)d_in[4];
    const float* Ad  = (const float*)d_in[5];
    const float* Bd  = (const float*)d_in[6];
    float* out = (float*)d_out;

    __nv_bfloat16 *Xe, *Wgue, *Ague, *Bgue, *Wde, *Ade, *Bde, *T1e, *T2e, *He;
    float *Pk;
    cudaGetSymbolAddress((void**)&Xe,   g_Xe);
    cudaGetSymbolAddress((void**)&Wgue, g_Wgue);
    cudaGetSymbolAddress((void**)&Ague, g_Ague);
    cudaGetSymbolAddress((void**)&Bgue, g_Bgue);
    cudaGetSymbolAddress((void**)&Wde,  g_Wde);
    cudaGetSymbolAddress((void**)&Ade,  g_Ade);
    cudaGetSymbolAddress((void**)&Bde,  g_Bde);
    cudaGetSymbolAddress((void**)&Pk,   g_Pk);
    cudaGetSymbolAddress((void**)&T1e,  g_T1e);
    cudaGetSymbolAddress((void**)&T2e,  g_T2e);
    cudaGetSymbolAddress((void**)&He,   g_He);

    cudaFuncSetAttribute(gemm_bf16x3<0>,
                         cudaFuncAttributeMaxDynamicSharedMemorySize, SMEM_BYTES);
    cudaFuncSetAttribute(gemm_bf16x3<1>,
                         cudaFuncAttributeMaxDynamicSharedMemorySize, SMEM_BYTES);
    cudaFuncSetAttribute(gemm_bf16x3<2>,
                         cudaFuncAttributeMaxDynamicSharedMemorySize, SMEM_BYTES);

    const int T = 256;
    auto g8 = [&](size_t n) { return (unsigned)((n / 8 + T - 1) / T); };

    { size_t n = (size_t)MTOK * HID;
      cvt_expand8<true ><<<g8(n), T>>>(X, Xe, n/8, 1.0f); }
    { size_t n = (size_t)2 * DEX * HID;
      cvt_expand8<false><<<g8(n), T>>>(Wgu, Wgue, n/8, 1.0f); }
    { size_t n = (size_t)RK * HID;
      cvt_expand8<false><<<g8(n), T>>>(Agu, Ague, n/8, 1.0f); }
    { size_t n = (size_t)2 * DEX * RK;
      cvt_expand8<false><<<g8(n), T>>>(Bgu, Bgue, n/8, 1.0f); }
    { size_t n = (size_t)HID * DEX;
      cvt_expand8<false><<<g8(n), T>>>(Wd, Wde, n/8, 1.0f); }
    { size_t n = (size_t)RK * DEX;
      cvt_expand8<false><<<g8(n), T>>>(Ad, Ade, n/8, 1.0f); }
    { size_t n = (size_t)HID * RK;
      cvt_expand8<false><<<g8(n), T>>>(Bd, Bde, n/8, 1.0f); }

    dim3 blk(NTH);
    const unsigned gr = (unsigned)(((size_t)MTOK * RK + T - 1) / T);

    gemm_bf16x3<2><<<dim3(1, MTOK/BM, SPLITK), blk, SMEM_BYTES>>>(
        Xe, Ague, nullptr, nullptr, Pk, RK, K1E, 0);
    reduce_expand<<<gr, T>>>(Pk, T1e);

    gemm_bf16x3<1><<<dim3(DEX/64, MTOK/BM), blk, SMEM_BYTES>>>(
        Xe, Wgue, T1e, Bgue, He, 2*DEX, K1E, KRE);

    gemm_bf16x3<2><<<dim3(1, MTOK/BM, SPLITK), blk, SMEM_BYTES>>>(
        He, Ade, nullptr, nullptr, Pk, RK, K2E, 0);
    reduce_expand<<<gr, T>>>(Pk, T2e);

    gemm_bf16x3<0><<<dim3(HID/BN, MTOK/BM), blk, SMEM_BYTES>>>(
        He, Wde, T2e, Bde, out, HID, K2E, KRE);
}

// round 7
// speedup vs baseline: 1.0402x; 1.0402x over previous
#include <cuda_runtime.h>
#include <cuda_bf16.h>
#include <cstdint>

#define MTOK 8192
#define HID  2048
#define DEX  4096
#define RK   64
#define K1E  (3*HID)   // 6144
#define K2E  (3*DEX)   // 12288
#define KRE  (3*RK)    // 192
#define SPLITK 4

// ---------------- scratch (device globals) ----------------------------------
__device__ __align__(16) __nv_bfloat16 g_Xe  [(size_t)MTOK * K1E];
__device__ __align__(16) __nv_bfloat16 g_Wgue[(size_t)2*DEX * K1E];
__device__ __align__(16) __nv_bfloat16 g_Ague[(size_t)RK * K1E];
__device__ __align__(16) __nv_bfloat16 g_Bgue[(size_t)2*DEX * KRE];
__device__ __align__(16) __nv_bfloat16 g_Wde [(size_t)HID * K2E];
__device__ __align__(16) __nv_bfloat16 g_Ade [(size_t)RK * K2E];
__device__ __align__(16) __nv_bfloat16 g_Bde [(size_t)HID * KRE];
__device__ __align__(16) float         g_Pk  [(size_t)SPLITK * MTOK * RK];
__device__ __align__(16) __nv_bfloat16 g_T1e [(size_t)MTOK * KRE];
__device__ __align__(16) __nv_bfloat16 g_T2e [(size_t)MTOK * KRE];
__device__ __align__(16) __nv_bfloat16 g_He  [(size_t)MTOK * K2E];

// ---------------- fp32 -> bf16x3 expansion (8 elems/thread) -----------------
template<bool ASIDE>
__global__ void cvt_expand8(const float* __restrict__ in,
                            __nv_bfloat16* __restrict__ out,
                            size_t n8, float scale) {
    size_t i = (size_t)blockIdx.x * blockDim.x + threadIdx.x;
    if (i >= n8) return;
    const float4* p = reinterpret_cast<const float4*>(in) + i * 2;
    float4 v0 = p[0], v1 = p[1];
    float x[8] = {v0.x, v0.y, v0.z, v0.w, v1.x, v1.y, v1.z, v1.w};
    __nv_bfloat16 ob[24];
#pragma unroll
    for (int k = 0; k < 8; k++) {
        float xv = x[k] * scale;
        __nv_bfloat16 hi = __float2bfloat16(xv);
        __nv_bfloat16 lo = __float2bfloat16(xv - __bfloat162float(hi));
        ob[3*k] = hi;
        if (ASIDE) { ob[3*k+1] = lo; ob[3*k+2] = hi; }
        else       { ob[3*k+1] = hi; ob[3*k+2] = lo; }
    }
    uint4* o = reinterpret_cast<uint4*>(out + i * 24);
    const uint4* s = reinterpret_cast<const uint4*>(ob);
    o[0] = s[0]; o[1] = s[1]; o[2] = s[2];
}

// ---------------- splitK reduce + 0.25 scale + A-side expansion -------------
__global__ void reduce_expand(const float* __restrict__ P,
                              __nv_bfloat16* __restrict__ out) {
    size_t idx = (size_t)blockIdx.x * blockDim.x + threadIdx.x;
    if (idx >= (size_t)MTOK * RK) return;
    const size_t S = (size_t)MTOK * RK;
    float s = P[idx] + P[idx + S] + P[idx + 2*S] + P[idx + 3*S];
    s *= 0.25f;                       // LORA_ALPHA / R
    __nv_bfloat16 hi = __float2bfloat16(s);
    __nv_bfloat16 lo = __float2bfloat16(s - __bfloat162float(hi));
    out[3*idx] = hi; out[3*idx+1] = lo; out[3*idx+2] = hi;
}

// ---------------- bf16 TN GEMM (mma.sync) -----------------------------------
// MODE 0: C fp32 [M][N], LoRA K-tail.   MODE 1: fused SwiGLU -> He bf16x3,
// gate/up interleaved B rows, n0 = d-offset.   MODE 2: splitK partial.
#define BM 128
#define BN 128
#define BKK 64
#define STAGES 3
#define NTH 256
#define TILE_BYTES (BM * BKK * 2)              // 16 KB
#define SMEM_BYTES (2 * STAGES * TILE_BYTES)   // 96 KB -> 2 CTAs/SM

template<int MODE>
__device__ __forceinline__ void load_tiles(uint32_t smem_u32, int stage,
                                           const __nv_bfloat16* gA,
                                           const __nv_bfloat16* gB,
                                           int m0, int n0, int N, int Ks,
                                           int kt, int tid) {
#pragma unroll
    for (int i = 0; i < 4; i++) {
        int c = tid + i * NTH;
        int row = c >> 3;
        int col = c & 7;
        uint32_t sw = (uint32_t)(col ^ (row & 7)) << 4;
        uint32_t da = smem_u32 + (uint32_t)stage * TILE_BYTES + row * 128 + sw;
        const void* sa = (const void*)(gA + (size_t)(m0 + row) * Ks
                                          + (size_t)kt * BKK + col * 8);
        asm volatile("cp.async.cg.shared.global [%0], [%1], 16;"
                     :: "r"(da), "l"(sa));
        int brow;
        if (MODE == 1) {
            brow = (row & 1) ? (DEX + n0 + (row >> 1)) : (n0 + (row >> 1));
        } else {
            brow = n0 + row; brow = brow < N ? brow : N - 1;  // clamp (N=64)
        }
        uint32_t db = smem_u32 + (uint32_t)(STAGES + stage) * TILE_BYTES
                               + row * 128 + sw;
        const void* sb = (const void*)(gB + (size_t)brow * Ks
                                          + (size_t)kt * BKK + col * 8);
        asm volatile("cp.async.cg.shared.global [%0], [%1], 16;"
                     :: "r"(db), "l"(sb));
    }
}

template<int MODE>
__global__ __launch_bounds__(NTH, 2) void gemm_bf16x3(
    const __nv_bfloat16* __restrict__ A,  const __nv_bfloat16* __restrict__ B,
    const __nv_bfloat16* __restrict__ A2, const __nv_bfloat16* __restrict__ B2,
    void* __restrict__ Cout, int N, int K, int Kt) {
    extern __shared__ char smem[];
    const uint32_t smem_u32 = (uint32_t)__cvta_generic_to_shared(smem);
    const int tid  = threadIdx.x;
    const int warp = tid >> 5, lane = tid & 31;
    const int wm = warp >> 2, wn = warp & 3;
    const int gid = lane >> 2, tig = lane & 3;

    // grouped CTA swizzle (8 y-tiles per x step) for L2 reuse of B panels
    int bx = blockIdx.x, by = blockIdx.y;
    if (MODE != 2 && gridDim.x > 1) {
        const int GRP = 8;
        int lin = by * gridDim.x + bx;
        int per = gridDim.x * GRP;
        int g   = lin / per, rem = lin % per;
        int gy  = g * GRP;
        int h   = gridDim.y - gy; if (h > GRP) h = GRP;
        by = gy + rem % h;
        bx = rem / h;
    }
    const int m0 = by * BM;
    const int n0 = bx * ((MODE == 1) ? 64 : BN);

    float acc[4][4][4];
#pragma unroll
    for (int a = 0; a < 4; a++)
#pragma unroll
        for (int b = 0; b < 4; b++)
#pragma unroll
            for (int c = 0; c < 4; c++) acc[a][b][c] = 0.0f;

    const int a_row_in = (lane & 15);
    const int a_ch_in  = (lane >> 4);
    const int b_row_in = ((lane >> 4) << 3) + (lane & 7);
    const int b_ch_in  = ((lane >> 3) & 1);

    const int cps   = (MODE == 2) ? (K / BKK) / SPLITK : 0;
    const int koff  = (MODE == 2) ? blockIdx.z * cps : 0;
    const int nseg  = (MODE == 2) ? 1 : 2;

    for (int seg = 0; seg < nseg; seg++) {
        const __nv_bfloat16* gA = seg ? A2 : A;
        const __nv_bfloat16* gB = seg ? B2 : B;
        const int Ks = seg ? Kt : K;
        if (Ks == 0) break;
        const int ktiles = (MODE == 2) ? cps : Ks / BKK;

        for (int p = 0; p < STAGES - 1; p++) {
            if (p < ktiles)
                load_tiles<MODE>(smem_u32, p, gA, gB, m0, n0, N, Ks,
                                 koff + p, tid);
            asm volatile("cp.async.commit_group;");
        }

        for (int kt = 0; kt < ktiles; kt++) {
            asm volatile("cp.async.wait_group %0;" :: "n"(STAGES - 2));
            __syncthreads();
            int nk = kt + STAGES - 1;
            if (nk < ktiles)
                load_tiles<MODE>(smem_u32, nk % STAGES, gA, gB, m0, n0, N, Ks,
                                 koff + nk, tid);
            asm volatile("cp.async.commit_group;");

            const int st = kt % STAGES;
            const uint32_t sA = smem_u32 + (uint32_t)st * TILE_BYTES;
            const uint32_t sB = smem_u32 + (uint32_t)(STAGES + st) * TILE_BYTES;
#pragma unroll
            for (int kk = 0; kk < BKK; kk += 16) {
                uint32_t ra[4][4];
#pragma unroll
                for (int mi = 0; mi < 4; mi++) {
                    int row = wm * 64 + mi * 16 + a_row_in;
                    int ch  = (kk >> 3) + a_ch_in;
                    uint32_t ad = sA + row * 128 + ((uint32_t)(ch ^ (row & 7)) << 4);
                    asm volatile(
                        "ldmatrix.sync.aligned.m8n8.x4.shared.b16 {%0,%1,%2,%3}, [%4];"
                        : "=r"(ra[mi][0]), "=r"(ra[mi][1]),
                          "=r"(ra[mi][2]), "=r"(ra[mi][3])
                        : "r"(ad));
                }
                uint32_t rb[4][2];
#pragma unroll
                for (int p = 0; p < 2; p++) {
                    int row = wn * 32 + p * 16 + b_row_in;
                    int ch  = (kk >> 3) + b_ch_in;
                    uint32_t bd = sB + row * 128 + ((uint32_t)(ch ^ (row & 7)) << 4);
                    asm volatile(
                        "ldmatrix.sync.aligned.m8n8.x4.shared.b16 {%0,%1,%2,%3}, [%4];"
                        : "=r"(rb[2*p][0]), "=r"(rb[2*p][1]),
                          "=r"(rb[2*p+1][0]), "=r"(rb[2*p+1][1])
                        : "r"(bd));
                }
#pragma unroll
                for (int mi = 0; mi < 4; mi++)
#pragma unroll
                    for (int ni = 0; ni < 4; ni++)
                        asm volatile(
                            "mma.sync.aligned.m16n8k16.row.col.f32.bf16.bf16.f32 "
                            "{%0,%1,%2,%3}, {%4,%5,%6,%7}, {%8,%9}, {%0,%1,%2,%3};"
                            : "+f"(acc[mi][ni][0]), "+f"(acc[mi][ni][1]),
                              "+f"(acc[mi][ni][2]), "+f"(acc[mi][ni][3])
                            : "r"(ra[mi][0]), "r"(ra[mi][1]),
                              "r"(ra[mi][2]), "r"(ra[mi][3]),
                              "r"(rb[ni][0]), "r"(rb[ni][1]));
            }
        }
        asm volatile("cp.async.wait_group 0;");
        __syncthreads();
    }

    if (MODE == 0) {
        float* C = (float*)Cout;
#pragma unroll
        for (int mi = 0; mi < 4; mi++) {
            int r0 = m0 + wm * 64 + mi * 16 + gid;
#pragma unroll
            for (int ni = 0; ni < 4; ni++) {
                int c0 = n0 + wn * 32 + ni * 8 + tig * 2;
                float2 v0 = make_float2(acc[mi][ni][0], acc[mi][ni][1]);
                float2 v1 = make_float2(acc[mi][ni][2], acc[mi][ni][3]);
                *reinterpret_cast<float2*>(C + (size_t)r0 * N + c0) = v0;
                *reinterpret_cast<float2*>(C + (size_t)(r0 + 8) * N + c0) = v1;
            }
        }
    } else if (MODE == 2) {
        float* C = (float*)Cout + (size_t)blockIdx.z * MTOK * RK;
#pragma unroll
        for (int mi = 0; mi < 4; mi++) {
            int r0 = m0 + wm * 64 + mi * 16 + gid;
#pragma unroll
            for (int ni = 0; ni < 4; ni++) {
                int c0 = wn * 32 + ni * 8 + tig * 2;
                if (c0 < RK) {
                    float2 v0 = make_float2(acc[mi][ni][0], acc[mi][ni][1]);
                    float2 v1 = make_float2(acc[mi][ni][2], acc[mi][ni][3]);
                    *reinterpret_cast<float2*>(C + (size_t)r0 * RK + c0) = v0;
                    *reinterpret_cast<float2*>(C + (size_t)(r0 + 8) * RK + c0) = v1;
                }
            }
        }
    } else {
        // MODE 1: acc pair (c0,c1) = (gate,up), local d = wn*16+ni*4+tig
        float* hs = reinterpret_cast<float*>(smem);   // [128][68] padded
#pragma unroll
        for (int mi = 0; mi < 4; mi++) {
            int rl = wm * 64 + mi * 16 + gid;
#pragma unroll
            for (int ni = 0; ni < 4; ni++) {
                int dl = wn * 16 + ni * 4 + tig;
                float g0 = acc[mi][ni][0], u0 = acc[mi][ni][1];
                hs[rl * 68 + dl]       = u0 * g0 / (1.0f + __expf(-g0));
                float g1 = acc[mi][ni][2], u1 = acc[mi][ni][3];
                hs[(rl + 8) * 68 + dl] = u1 * g1 / (1.0f + __expf(-g1));
            }
        }
        __syncthreads();
        __nv_bfloat16* He = (__nv_bfloat16*)Cout;
#pragma unroll
        for (int it = 0; it < 4; it++) {
            int rl  = it * 32 + (tid >> 3);
            int blk = tid & 7;
            float4 v0 = *reinterpret_cast<float4*>(&hs[rl * 68 + blk * 8]);
            float4 v1 = *reinterpret_cast<float4*>(&hs[rl * 68 + blk * 8 + 4]);
            float x[8] = {v0.x, v0.y, v0.z, v0.w, v1.x, v1.y, v1.z, v1.w};
            __nv_bfloat16 ob[24];
#pragma unroll
            for (int k = 0; k < 8; k++) {
                __nv_bfloat16 hi = __float2bfloat16(x[k]);
                __nv_bfloat16 lo = __float2bfloat16(x[k] - __bfloat162float(hi));
                ob[3*k] = hi; ob[3*k+1] = lo; ob[3*k+2] = hi;
            }
            uint4* o = reinterpret_cast<uint4*>(
                He + (size_t)(m0 + rl) * K2E + 3 * (n0 + blk * 8));
            const uint4* s = reinterpret_cast<const uint4*>(ob);
            o[0] = s[0]; o[1] = s[1]; o[2] = s[2];
        }
    }
}

// ---------------- launcher ---------------------------------------------------
extern "C" void kernel_launch(void* const* d_in, const int* in_sizes, int n_in,
                              void* d_out, int out_size) {
    const float* X   = (const float*)d_in[0];
    const float* Wgu = (const float*)d_in[1];
    const float* Agu = (const float*)d_in[2];
    const float* Bgu = (const float*)d_in[3];
    const float* Wd  = (const float*)d_in[4];
    const float* Ad  = (const float*)d_in[5];
    const float* Bd  = (const float*)d_in[6];
    float* out = (float*)d_out;

    __nv_bfloat16 *Xe, *Wgue, *Ague, *Bgue, *Wde, *Ade, *Bde, *T1e, *T2e, *He;
    float *Pk;
    cudaGetSymbolAddress((void**)&Xe,   g_Xe);
    cudaGetSymbolAddress((void**)&Wgue, g_Wgue);
    cudaGetSymbolAddress((void**)&Ague, g_Ague);
    cudaGetSymbolAddress((void**)&Bgue, g_Bgue);
    cudaGetSymbolAddress((void**)&Wde,  g_Wde);
    cudaGetSymbolAddress((void**)&Ade,  g_Ade);
    cudaGetSymbolAddress((void**)&Bde,  g_Bde);
    cudaGetSymbolAddress((void**)&Pk,   g_Pk);
    cudaGetSymbolAddress((void**)&T1e,  g_T1e);
    cudaGetSymbolAddress((void**)&T2e,  g_T2e);
    cudaGetSymbolAddress((void**)&He,   g_He);

    cudaFuncSetAttribute(gemm_bf16x3<0>,
                         cudaFuncAttributeMaxDynamicSharedMemorySize, SMEM_BYTES);
    cudaFuncSetAttribute(gemm_bf16x3<1>,
                         cudaFuncAttributeMaxDynamicSharedMemorySize, SMEM_BYTES);
    cudaFuncSetAttribute(gemm_bf16x3<2>,
                         cudaFuncAttributeMaxDynamicSharedMemorySize, SMEM_BYTES);

    const int T = 256;
    auto g8 = [&](size_t n) { return (unsigned)((n / 8 + T - 1) / T); };

    { size_t n = (size_t)MTOK * HID;
      cvt_expand8<true ><<<g8(n), T>>>(X, Xe, n/8, 1.0f); }
    { size_t n = (size_t)2 * DEX * HID;
      cvt_expand8<false><<<g8(n), T>>>(Wgu, Wgue, n/8, 1.0f); }
    { size_t n = (size_t)RK * HID;
      cvt_expand8<false><<<g8(n), T>>>(Agu, Ague, n/8, 1.0f); }
    { size_t n = (size_t)2 * DEX * RK;
      cvt_expand8<false><<<g8(n), T>>>(Bgu, Bgue, n/8, 1.0f); }
    { size_t n = (size_t)HID * DEX;
      cvt_expand8<false><<<g8(n), T>>>(Wd, Wde, n/8, 1.0f); }
    { size_t n = (size_t)RK * DEX;
      cvt_expand8<false><<<g8(n), T>>>(Ad, Ade, n/8, 1.0f); }
    { size_t n = (size_t)HID * RK;
      cvt_expand8<false><<<g8(n), T>>>(Bd, Bde, n/8, 1.0f); }

    dim3 blk(NTH);
    const unsigned gr = (unsigned)(((size_t)MTOK * RK + T - 1) / T);

    gemm_bf16x3<2><<<dim3(1, MTOK/BM, SPLITK), blk, SMEM_BYTES>>>(
        Xe, Ague, nullptr, nullptr, Pk, RK, K1E, 0);
    reduce_expand<<<gr, T>>>(Pk, T1e);

    gemm_bf16x3<1><<<dim3(DEX/64, MTOK/BM), blk, SMEM_BYTES>>>(
        Xe, Wgue, T1e, Bgue, He, 2*DEX, K1E, KRE);

    gemm_bf16x3<2><<<dim3(1, MTOK/BM, SPLITK), blk, SMEM_BYTES>>>(
        He, Ade, nullptr, nullptr, Pk, RK, K2E, 0);
    reduce_expand<<<gr, T>>>(Pk, T2e);

    gemm_bf16x3<0><<<dim3(HID/BN, MTOK/BM), blk, SMEM_BYTES>>>(
        He, Wde, T2e, Bde, out, HID, K2E, KRE);
}

// round 8
// speedup vs baseline: 1.5222x; 1.4633x over previous
#include <cuda_runtime.h>
#include <cuda_fp16.h>
#include <cstdint>

#define MTOK 8192
#define HID  2048
#define DEX  4096
#define RK   64
#define K1E  (2*HID)   // 4096  (fp16 pair expansion)
#define K2E  (2*DEX)   // 8192
#define KRE  (2*RK)    // 128
#define SPLITK 4
// scaling: A-side stored = 16*true, B-side = 64*true, GEMM raw = 1024*true
#define INV_GEMM (1.0f/1024.0f)

// ---------------- scratch (device globals) ----------------------------------
__device__ __align__(16) __half g_Xe  [(size_t)MTOK * K1E];
__device__ __align__(16) __half g_Wgue[(size_t)2*DEX * K1E];
__device__ __align__(16) __half g_Ague[(size_t)RK * K1E];
__device__ __align__(16) __half g_Bgue[(size_t)2*DEX * KRE];
__device__ __align__(16) __half g_Wde [(size_t)HID * K2E];
__device__ __align__(16) __half g_Ade [(size_t)RK * K2E];
__device__ __align__(16) __half g_Bde [(size_t)HID * KRE];
__device__ __align__(16) float  g_Pk  [(size_t)SPLITK * MTOK * RK];
__device__ __align__(16) __half g_T1e [(size_t)MTOK * KRE];
__device__ __align__(16) __half g_T2e [(size_t)MTOK * KRE];
__device__ __align__(16) __half g_He  [(size_t)MTOK * K2E];

// ---------------- fp32 -> fp16x2 expansion (8 elems/thread) -----------------
// A-side [hi,lo] x B-side [hi,hi] -> (a_hi+a_lo)*b_hi = a*b_hi; missing term
// a*b_lo ~ 2^-12 incoherent. scale keeps lo in fp16 normal range.
template<bool ASIDE>
__global__ void cvt_expand8(const float* __restrict__ in,
                            __half* __restrict__ out,
                            size_t n8, float scale) {
    size_t i = (size_t)blockIdx.x * blockDim.x + threadIdx.x;
    if (i >= n8) return;
    const float4* p = reinterpret_cast<const float4*>(in) + i * 2;
    float4 v0 = p[0], v1 = p[1];
    float x[8] = {v0.x, v0.y, v0.z, v0.w, v1.x, v1.y, v1.z, v1.w};
    __half ob[16];
#pragma unroll
    for (int k = 0; k < 8; k++) {
        float xv = x[k] * scale;
        __half hi = __float2half_rn(xv);
        ob[2*k] = hi;
        if (ASIDE) ob[2*k+1] = __float2half_rn(xv - __half2float(hi));
        else       ob[2*k+1] = hi;
    }
    uint4* o = reinterpret_cast<uint4*>(out + i * 16);
    const uint4* s = reinterpret_cast<const uint4*>(ob);
    o[0] = s[0]; o[1] = s[1];
}

// ---------------- splitK reduce + scale + A-side fp16 pair ------------------
// raw = 1024*true; want A-side of 0.25*true*16 => raw * (0.25*16/1024) = raw/256
__global__ void reduce_expand(const float* __restrict__ P,
                              __half* __restrict__ out) {
    size_t idx = (size_t)blockIdx.x * blockDim.x + threadIdx.x;
    if (idx >= (size_t)MTOK * RK) return;
    const size_t S = (size_t)MTOK * RK;
    float s = (P[idx] + P[idx + S] + P[idx + 2*S] + P[idx + 3*S]) * (1.0f/256.0f);
    __half hi = __float2half_rn(s);
    out[2*idx]   = hi;
    out[2*idx+1] = __float2half_rn(s - __half2float(hi));
}

// ---------------- fp16 TN GEMM (mma.sync) -----------------------------------
// MODE 0: C fp32 [M][N] (descaled), LoRA K-tail.  MODE 1: fused SwiGLU -> He
// fp16 pairs, gate/up interleaved B rows, n0 = d-offset.  MODE 2: splitK raw.
#define BM 128
#define BN 128
#define BKK 64
#define STAGES 3
#define NTH 256
#define TILE_BYTES (BM * BKK * 2)              // 16 KB
#define SMEM_BYTES (2 * STAGES * TILE_BYTES)   // 96 KB -> 2 CTAs/SM

template<int MODE>
__device__ __forceinline__ void load_tiles(uint32_t smem_u32, int stage,
                                           const __half* gA,
                                           const __half* gB,
                                           int m0, int n0, int N, int Ks,
                                           int kt, int tid) {
#pragma unroll
    for (int i = 0; i < 4; i++) {
        int c = tid + i * NTH;
        int row = c >> 3;
        int col = c & 7;
        uint32_t sw = (uint32_t)(col ^ (row & 7)) << 4;
        uint32_t da = smem_u32 + (uint32_t)stage * TILE_BYTES + row * 128 + sw;
        const void* sa = (const void*)(gA + (size_t)(m0 + row) * Ks
                                          + (size_t)kt * BKK + col * 8);
        asm volatile("cp.async.cg.shared.global [%0], [%1], 16;"
                     :: "r"(da), "l"(sa));
        int brow;
        if (MODE == 1) {
            brow = (row & 1) ? (DEX + n0 + (row >> 1)) : (n0 + (row >> 1));
        } else {
            brow = n0 + row; brow = brow < N ? brow : N - 1;  // clamp (N=64)
        }
        uint32_t db = smem_u32 + (uint32_t)(STAGES + stage) * TILE_BYTES
                               + row * 128 + sw;
        const void* sb = (const void*)(gB + (size_t)brow * Ks
                                          + (size_t)kt * BKK + col * 8);
        asm volatile("cp.async.cg.shared.global [%0], [%1], 16;"
                     :: "r"(db), "l"(sb));
    }
}

template<int MODE>
__global__ __launch_bounds__(NTH, 2) void gemm_fp16x2(
    const __half* __restrict__ A,  const __half* __restrict__ B,
    const __half* __restrict__ A2, const __half* __restrict__ B2,
    void* __restrict__ Cout, int N, int K, int Kt) {
    extern __shared__ char smem[];
    const uint32_t smem_u32 = (uint32_t)__cvta_generic_to_shared(smem);
    const int tid  = threadIdx.x;
    const int warp = tid >> 5, lane = tid & 31;
    const int wm = warp >> 2, wn = warp & 3;
    const int gid = lane >> 2, tig = lane & 3;

    // grouped CTA swizzle (8 y-tiles per x step) for L2 reuse of B panels
    int bx = blockIdx.x, by = blockIdx.y;
    if (MODE != 2 && gridDim.x > 1) {
        const int GRP = 8;
        int lin = by * gridDim.x + bx;
        int per = gridDim.x * GRP;
        int g   = lin / per, rem = lin % per;
        int gy  = g * GRP;
        int h   = gridDim.y - gy; if (h > GRP) h = GRP;
        by = gy + rem % h;
        bx = rem / h;
    }
    const int m0 = by * BM;
    const int n0 = bx * ((MODE == 1) ? 64 : BN);

    float acc[4][4][4];
#pragma unroll
    for (int a = 0; a < 4; a++)
#pragma unroll
        for (int b = 0; b < 4; b++)
#pragma unroll
            for (int c = 0; c < 4; c++) acc[a][b][c] = 0.0f;

    const int a_row_in = (lane & 15);
    const int a_ch_in  = (lane >> 4);
    const int b_row_in = ((lane >> 4) << 3) + (lane & 7);
    const int b_ch_in  = ((lane >> 3) & 1);

    const int cps   = (MODE == 2) ? (K / BKK) / SPLITK : 0;
    const int koff  = (MODE == 2) ? blockIdx.z * cps : 0;
    const int nseg  = (MODE == 2) ? 1 : 2;

    for (int seg = 0; seg < nseg; seg++) {
        const __half* gA = seg ? A2 : A;
        const __half* gB = seg ? B2 : B;
        const int Ks = seg ? Kt : K;
        if (Ks == 0) break;
        const int ktiles = (MODE == 2) ? cps : Ks / BKK;

        for (int p = 0; p < STAGES - 1; p++) {
            if (p < ktiles)
                load_tiles<MODE>(smem_u32, p, gA, gB, m0, n0, N, Ks,
                                 koff + p, tid);
            asm volatile("cp.async.commit_group;");
        }

        for (int kt = 0; kt < ktiles; kt++) {
            asm volatile("cp.async.wait_group %0;" :: "n"(STAGES - 2));
            __syncthreads();
            int nk = kt + STAGES - 1;
            if (nk < ktiles)
                load_tiles<MODE>(smem_u32, nk % STAGES, gA, gB, m0, n0, N, Ks,
                                 koff + nk, tid);
            asm volatile("cp.async.commit_group;");

            const int st = kt % STAGES;
            const uint32_t sA = smem_u32 + (uint32_t)st * TILE_BYTES;
            const uint32_t sB = smem_u32 + (uint32_t)(STAGES + st) * TILE_BYTES;
#pragma unroll
            for (int kk = 0; kk < BKK; kk += 16) {
                uint32_t ra[4][4];
#pragma unroll
                for (int mi = 0; mi < 4; mi++) {
                    int row = wm * 64 + mi * 16 + a_row_in;
                    int ch  = (kk >> 3) + a_ch_in;
                    uint32_t ad = sA + row * 128 + ((uint32_t)(ch ^ (row & 7)) << 4);
                    asm volatile(
                        "ldmatrix.sync.aligned.m8n8.x4.shared.b16 {%0,%1,%2,%3}, [%4];"
                        : "=r"(ra[mi][0]), "=r"(ra[mi][1]),
                          "=r"(ra[mi][2]), "=r"(ra[mi][3])
                        : "r"(ad));
                }
                uint32_t rb[4][2];
#pragma unroll
                for (int p = 0; p < 2; p++) {
                    int row = wn * 32 + p * 16 + b_row_in;
                    int ch  = (kk >> 3) + b_ch_in;
                    uint32_t bd = sB + row * 128 + ((uint32_t)(ch ^ (row & 7)) << 4);
                    asm volatile(
                        "ldmatrix.sync.aligned.m8n8.x4.shared.b16 {%0,%1,%2,%3}, [%4];"
                        : "=r"(rb[2*p][0]), "=r"(rb[2*p][1]),
                          "=r"(rb[2*p+1][0]), "=r"(rb[2*p+1][1])
                        : "r"(bd));
                }
#pragma unroll
                for (int mi = 0; mi < 4; mi++)
#pragma unroll
                    for (int ni = 0; ni < 4; ni++)
                        asm volatile(
                            "mma.sync.aligned.m16n8k16.row.col.f32.f16.f16.f32 "
                            "{%0,%1,%2,%3}, {%4,%5,%6,%7}, {%8,%9}, {%0,%1,%2,%3};"
                            : "+f"(acc[mi][ni][0]), "+f"(acc[mi][ni][1]),
                              "+f"(acc[mi][ni][2]), "+f"(acc[mi][ni][3])
                            : "r"(ra[mi][0]), "r"(ra[mi][1]),
                              "r"(ra[mi][2]), "r"(ra[mi][3]),
                              "r"(rb[ni][0]), "r"(rb[ni][1]));
            }
        }
        asm volatile("cp.async.wait_group 0;");
        __syncthreads();
    }

    if (MODE == 0) {
        float* C = (float*)Cout;
#pragma unroll
        for (int mi = 0; mi < 4; mi++) {
            int r0 = m0 + wm * 64 + mi * 16 + gid;
#pragma unroll
            for (int ni = 0; ni < 4; ni++) {
                int c0 = n0 + wn * 32 + ni * 8 + tig * 2;
                float2 v0 = make_float2(acc[mi][ni][0] * INV_GEMM,
                                        acc[mi][ni][1] * INV_GEMM);
                float2 v1 = make_float2(acc[mi][ni][2] * INV_GEMM,
                                        acc[mi][ni][3] * INV_GEMM);
                *reinterpret_cast<float2*>(C + (size_t)r0 * N + c0) = v0;
                *reinterpret_cast<float2*>(C + (size_t)(r0 + 8) * N + c0) = v1;
            }
        }
    } else if (MODE == 2) {
        float* C = (float*)Cout + (size_t)blockIdx.z * MTOK * RK;
#pragma unroll
        for (int mi = 0; mi < 4; mi++) {
            int r0 = m0 + wm * 64 + mi * 16 + gid;
#pragma unroll
            for (int ni = 0; ni < 4; ni++) {
                int c0 = wn * 32 + ni * 8 + tig * 2;
                if (c0 < RK) {
                    float2 v0 = make_float2(acc[mi][ni][0], acc[mi][ni][1]);
                    float2 v1 = make_float2(acc[mi][ni][2], acc[mi][ni][3]);
                    *reinterpret_cast<float2*>(C + (size_t)r0 * RK + c0) = v0;
                    *reinterpret_cast<float2*>(C + (size_t)(r0 + 8) * RK + c0) = v1;
                }
            }
        }
    } else {
        // MODE 1: acc pair (c0,c1) = (gate,up) raw (x1024); local d = wn*16+ni*4+tig
        float* hs = reinterpret_cast<float*>(smem);   // [128][68] padded
#pragma unroll
        for (int mi = 0; mi < 4; mi++) {
            int rl = wm * 64 + mi * 16 + gid;
#pragma unroll
            for (int ni = 0; ni < 4; ni++) {
                int dl = wn * 16 + ni * 4 + tig;
                float g0 = acc[mi][ni][0] * INV_GEMM, u0 = acc[mi][ni][1] * INV_GEMM;
                hs[rl * 68 + dl]       = u0 * g0 / (1.0f + __expf(-g0));
                float g1 = acc[mi][ni][2] * INV_GEMM, u1 = acc[mi][ni][3] * INV_GEMM;
                hs[(rl + 8) * 68 + dl] = u1 * g1 / (1.0f + __expf(-g1));
            }
        }
        __syncthreads();
        __half* He = (__half*)Cout;
#pragma unroll
        for (int it = 0; it < 4; it++) {
            int rl  = it * 32 + (tid >> 3);
            int blk = tid & 7;
            float4 v0 = *reinterpret_cast<float4*>(&hs[rl * 68 + blk * 8]);
            float4 v1 = *reinterpret_cast<float4*>(&hs[rl * 68 + blk * 8 + 4]);
            float x[8] = {v0.x, v0.y, v0.z, v0.w, v1.x, v1.y, v1.z, v1.w};
            __half ob[16];
#pragma unroll
            for (int k = 0; k < 8; k++) {
                float xv = x[k] * 16.0f;              // A-side scale
                __half hi = __float2half_rn(xv);
                ob[2*k] = hi;
                ob[2*k+1] = __float2half_rn(xv - __half2float(hi));
            }
            uint4* o = reinterpret_cast<uint4*>(
                He + (size_t)(m0 + rl) * K2E + 2 * (n0 + blk * 8));
            const uint4* s = reinterpret_cast<const uint4*>(ob);
            o[0] = s[0]; o[1] = s[1];
        }
    }
}

// ---------------- launcher ---------------------------------------------------
extern "C" void kernel_launch(void* const* d_in, const int* in_sizes, int n_in,
                              void* d_out, int out_size) {
    const float* X   = (const float*)d_in[0];
    const float* Wgu = (const float*)d_in[1];
    const float* Agu = (const float*)d_in[2];
    const float* Bgu = (const float*)d_in[3];
    const float* Wd  = (const float*)d_in[4];
    const float* Ad  = (const float*)d_in[5];
    const float* Bd  = (const float*)d_in[6];
    float* out = (float*)d_out;

    __half *Xe, *Wgue, *Ague, *Bgue, *Wde, *Ade, *Bde, *T1e, *T2e, *He;
    float *Pk;
    cudaGetSymbolAddress((void**)&Xe,   g_Xe);
    cudaGetSymbolAddress((void**)&Wgue, g_Wgue);
    cudaGetSymbolAddress((void**)&Ague, g_Ague);
    cudaGetSymbolAddress((void**)&Bgue, g_Bgue);
    cudaGetSymbolAddress((void**)&Wde,  g_Wde);
    cudaGetSymbolAddress((void**)&Ade,  g_Ade);
    cudaGetSymbolAddress((void**)&Bde,  g_Bde);
    cudaGetSymbolAddress((void**)&Pk,   g_Pk);
    cudaGetSymbolAddress((void**)&T1e,  g_T1e);
    cudaGetSymbolAddress((void**)&T2e,  g_T2e);
    cudaGetSymbolAddress((void**)&He,   g_He);

    cudaFuncSetAttribute(gemm_fp16x2<0>,
                         cudaFuncAttributeMaxDynamicSharedMemorySize, SMEM_BYTES);
    cudaFuncSetAttribute(gemm_fp16x2<1>,
                         cudaFuncAttributeMaxDynamicSharedMemorySize, SMEM_BYTES);
    cudaFuncSetAttribute(gemm_fp16x2<2>,
                         cudaFuncAttributeMaxDynamicSharedMemorySize, SMEM_BYTES);

    const int T = 256;
    auto g8 = [&](size_t n) { return (unsigned)((n / 8 + T - 1) / T); };

    // A-side: scale 16;  B-side: scale 64
    { size_t n = (size_t)MTOK * HID;
      cvt_expand8<true ><<<g8(n), T>>>(X, Xe, n/8, 16.0f); }
    { size_t n = (size_t)2 * DEX * HID;
      cvt_expand8<false><<<g8(n), T>>>(Wgu, Wgue, n/8, 64.0f); }
    { size_t n = (size_t)RK * HID;
      cvt_expand8<false><<<g8(n), T>>>(Agu, Ague, n/8, 64.0f); }
    { size_t n = (size_t)2 * DEX * RK;
      cvt_expand8<false><<<g8(n), T>>>(Bgu, Bgue, n/8, 64.0f); }
    { size_t n = (size_t)HID * DEX;
      cvt_expand8<false><<<g8(n), T>>>(Wd, Wde, n/8, 64.0f); }
    { size_t n = (size_t)RK * DEX;
      cvt_expand8<false><<<g8(n), T>>>(Ad, Ade, n/8, 64.0f); }
    { size_t n = (size_t)HID * RK;
      cvt_expand8<false><<<g8(n), T>>>(Bd, Bde, n/8, 64.0f); }

    dim3 blk(NTH);
    const unsigned gr = (unsigned)(((size_t)MTOK * RK + T - 1) / T);

    // T1 raw = 1024*(X @ Agu^T), splitK x4 -> reduce(/256) -> T1e fp16 pairs
    gemm_fp16x2<2><<<dim3(1, MTOK/BM, SPLITK), blk, SMEM_BYTES>>>(
        Xe, Ague, nullptr, nullptr, Pk, RK, K1E, 0);
    reduce_expand<<<gr, T>>>(Pk, T1e);

    // He = 16*swiglu((X@Wgu^T + 0.25*T1@Bgu^T)), fp16 pairs
    gemm_fp16x2<1><<<dim3(DEX/64, MTOK/BM), blk, SMEM_BYTES>>>(
        Xe, Wgue, T1e, Bgue, He, 2*DEX, K1E, KRE);

    // T2 raw, splitK x4 -> reduce -> T2e
    gemm_fp16x2<2><<<dim3(1, MTOK/BM, SPLITK), blk, SMEM_BYTES>>>(
        He, Ade, nullptr, nullptr, Pk, RK, K2E, 0);
    reduce_expand<<<gr, T>>>(Pk, T2e);

    // out = (H@Wd^T + 0.25*T2@Bd^T), descaled in epilogue
    gemm_fp16x2<0><<<dim3(HID/BN, MTOK/BM), blk, SMEM_BYTES>>>(
        He, Wde, T2e, Bde, out, HID, K2E, KRE);
}

// round 9
// speedup vs baseline: 1.8015x; 1.1835x over previous
#include <cuda_runtime.h>
#include <cuda_fp16.h>
#include <cstdint>

#define MTOK 8192
#define HID  2048
#define DEX  4096
#define RK   64
#define K1E  (2*HID)   // 4096  GEMM1 K (A split hi/lo, B dup)
#define K2P  DEX       // 4096  GEMM2 K (both sides plain fp16)
#define KRE  (2*RK)    // 128   LoRA tail K (expanded)
#define SPLITK 4
// scaling: A-side stored = 16*true, B-side = 64*true, GEMM raw = 1024*true
#define INV_GEMM (1.0f/1024.0f)

// ---------------- scratch (device globals) ----------------------------------
__device__ __align__(16) __half g_Xe  [(size_t)MTOK * K1E];
__device__ __align__(16) __half g_Wgue[(size_t)2*DEX * K1E];
__device__ __align__(16) __half g_Ague[(size_t)RK * K1E];
__device__ __align__(16) __half g_Bgue[(size_t)2*DEX * KRE];
__device__ __align__(16) __half g_Wde [(size_t)HID * K2P];   // plain
__device__ __align__(16) __half g_Ade [(size_t)RK * K2P];    // plain
__device__ __align__(16) __half g_Bde [(size_t)HID * KRE];
__device__ __align__(16) float  g_Pk  [(size_t)SPLITK * MTOK * RK];
__device__ __align__(16) __half g_T1e [(size_t)MTOK * KRE];
__device__ __align__(16) __half g_T2e [(size_t)MTOK * KRE];
__device__ __align__(16) __half g_He  [(size_t)MTOK * K2P];  // plain

// ---------------- fp32 -> fp16x2 expansion (8 elems/thread) -----------------
template<bool ASIDE>
__global__ void cvt_expand8(const float* __restrict__ in,
                            __half* __restrict__ out,
                            size_t n8, float scale) {
    size_t i = (size_t)blockIdx.x * blockDim.x + threadIdx.x;
    if (i >= n8) return;
    const float4* p = reinterpret_cast<const float4*>(in) + i * 2;
    float4 v0 = p[0], v1 = p[1];
    float x[8] = {v0.x, v0.y, v0.z, v0.w, v1.x, v1.y, v1.z, v1.w};
    __half ob[16];
#pragma unroll
    for (int k = 0; k < 8; k++) {
        float xv = x[k] * scale;
        __half hi = __float2half_rn(xv);
        ob[2*k] = hi;
        if (ASIDE) ob[2*k+1] = __float2half_rn(xv - __half2float(hi));
        else       ob[2*k+1] = hi;
    }
    uint4* o = reinterpret_cast<uint4*>(out + i * 16);
    const uint4* s = reinterpret_cast<const uint4*>(ob);
    o[0] = s[0]; o[1] = s[1];
}

// ---------------- fp32 -> plain fp16 (8 elems/thread) -----------------------
__global__ void cvt_plain8(const float* __restrict__ in,
                           __half* __restrict__ out,
                           size_t n8, float scale) {
    size_t i = (size_t)blockIdx.x * blockDim.x + threadIdx.x;
    if (i >= n8) return;
    const float4* p = reinterpret_cast<const float4*>(in) + i * 2;
    float4 v0 = p[0], v1 = p[1];
    float x[8] = {v0.x, v0.y, v0.z, v0.w, v1.x, v1.y, v1.z, v1.w};
    __half ob[8];
#pragma unroll
    for (int k = 0; k < 8; k++) ob[k] = __float2half_rn(x[k] * scale);
    *reinterpret_cast<uint4*>(out + i * 8) = *reinterpret_cast<const uint4*>(ob);
}

// ---------------- splitK reduce + scale + A-side fp16 pair ------------------
// raw = 1024*true; A-side of 0.25*true*16 => raw/256
__global__ void reduce_expand(const float* __restrict__ P,
                              __half* __restrict__ out) {
    size_t idx = (size_t)blockIdx.x * blockDim.x + threadIdx.x;
    if (idx >= (size_t)MTOK * RK) return;
    const size_t S = (size_t)MTOK * RK;
    float s = (P[idx] + P[idx + S] + P[idx + 2*S] + P[idx + 3*S]) * (1.0f/256.0f);
    __half hi = __float2half_rn(s);
    out[2*idx]   = hi;
    out[2*idx+1] = __float2half_rn(s - __half2float(hi));
}

// ---------------- fp16 TN GEMM (mma.sync) -----------------------------------
// MODE 0: C fp32 (descaled), LoRA K-tail.  MODE 1: fused SwiGLU -> He plain
// fp16 (x16), gate/up interleaved B rows, n0 = d-offset.  MODE 2: splitK raw.
#define BM 128
#define BN 128
#define BKK 64
#define STAGES 3
#define NTH 256
#define TILE_BYTES (BM * BKK * 2)              // 16 KB
#define SMEM_BYTES (2 * STAGES * TILE_BYTES)   // 96 KB -> 2 CTAs/SM

template<int MODE>
__device__ __forceinline__ void load_tiles(uint32_t smem_u32, int stage,
                                           const __half* gA,
                                           const __half* gB,
                                           int m0, int n0, int N, int Ks,
                                           int kt, int tid) {
#pragma unroll
    for (int i = 0; i < 4; i++) {
        int c = tid + i * NTH;
        int row = c >> 3;
        int col = c & 7;
        uint32_t sw = (uint32_t)(col ^ (row & 7)) << 4;
        uint32_t da = smem_u32 + (uint32_t)stage * TILE_BYTES + row * 128 + sw;
        const void* sa = (const void*)(gA + (size_t)(m0 + row) * Ks
                                          + (size_t)kt * BKK + col * 8);
        asm volatile("cp.async.cg.shared.global [%0], [%1], 16;"
                     :: "r"(da), "l"(sa));
        int brow;
        if (MODE == 1) {
            brow = (row & 1) ? (DEX + n0 + (row >> 1)) : (n0 + (row >> 1));
        } else {
            brow = n0 + row; brow = brow < N ? brow : N - 1;  // clamp (N=64)
        }
        uint32_t db = smem_u32 + (uint32_t)(STAGES + stage) * TILE_BYTES
                               + row * 128 + sw;
        const void* sb = (const void*)(gB + (size_t)brow * Ks
                                          + (size_t)kt * BKK + col * 8);
        asm volatile("cp.async.cg.shared.global [%0], [%1], 16;"
                     :: "r"(db), "l"(sb));
    }
}

template<int MODE>
__global__ __launch_bounds__(NTH, 2) void gemm_fp16(
    const __half* __restrict__ A,  const __half* __restrict__ B,
    const __half* __restrict__ A2, const __half* __restrict__ B2,
    void* __restrict__ Cout, int N, int K, int Kt) {
    extern __shared__ char smem[];
    const uint32_t smem_u32 = (uint32_t)__cvta_generic_to_shared(smem);
    const int tid  = threadIdx.x;
    const int warp = tid >> 5, lane = tid & 31;
    const int wm = warp >> 2, wn = warp & 3;
    const int gid = lane >> 2, tig = lane & 3;

    // grouped CTA swizzle (8 y-tiles per x step) for L2 reuse of B panels
    int bx = blockIdx.x, by = blockIdx.y;
    if (MODE != 2 && gridDim.x > 1) {
        const int GRP = 8;
        int lin = by * gridDim.x + bx;
        int per = gridDim.x * GRP;
        int g   = lin / per, rem = lin % per;
        int gy  = g * GRP;
        int h   = gridDim.y - gy; if (h > GRP) h = GRP;
        by = gy + rem % h;
        bx = rem / h;
    }
    const int m0 = by * BM;
    const int n0 = bx * ((MODE == 1) ? 64 : BN);

    float acc[4][4][4];
#pragma unroll
    for (int a = 0; a < 4; a++)
#pragma unroll
        for (int b = 0; b < 4; b++)
#pragma unroll
            for (int c = 0; c < 4; c++) acc[a][b][c] = 0.0f;

    const int a_row_in = (lane & 15);
    const int a_ch_in  = (lane >> 4);
    const int b_row_in = ((lane >> 4) << 3) + (lane & 7);
    const int b_ch_in  = ((lane >> 3) & 1);

    const int cps   = (MODE == 2) ? (K / BKK) / SPLITK : 0;
    const int koff  = (MODE == 2) ? blockIdx.z * cps : 0;
    const int nseg  = (MODE == 2) ? 1 : 2;

    for (int seg = 0; seg < nseg; seg++) {
        const __half* gA = seg ? A2 : A;
        const __half* gB = seg ? B2 : B;
        const int Ks = seg ? Kt : K;
        if (Ks == 0) break;
        const int ktiles = (MODE == 2) ? cps : Ks / BKK;

        for (int p = 0; p < STAGES - 1; p++) {
            if (p < ktiles)
                load_tiles<MODE>(smem_u32, p, gA, gB, m0, n0, N, Ks,
                                 koff + p, tid);
            asm volatile("cp.async.commit_group;");
        }

        for (int kt = 0; kt < ktiles; kt++) {
            asm volatile("cp.async.wait_group %0;" :: "n"(STAGES - 2));
            __syncthreads();

            const int st = kt % STAGES;
            const uint32_t sA = smem_u32 + (uint32_t)st * TILE_BYTES;
            const uint32_t sB = smem_u32 + (uint32_t)(STAGES + st) * TILE_BYTES;

            uint32_t ra[4][4], rb[4][2];
            auto frags = [&](int kk) {
#pragma unroll
                for (int mi = 0; mi < 4; mi++) {
                    int row = wm * 64 + mi * 16 + a_row_in;
                    int ch  = (kk >> 3) + a_ch_in;
                    uint32_t ad = sA + row * 128 + ((uint32_t)(ch ^ (row & 7)) << 4);
                    asm volatile(
                        "ldmatrix.sync.aligned.m8n8.x4.shared.b16 {%0,%1,%2,%3}, [%4];"
                        : "=r"(ra[mi][0]), "=r"(ra[mi][1]),
                          "=r"(ra[mi][2]), "=r"(ra[mi][3])
                        : "r"(ad));
                }
#pragma unroll
                for (int p = 0; p < 2; p++) {
                    int row = wn * 32 + p * 16 + b_row_in;
                    int ch  = (kk >> 3) + b_ch_in;
                    uint32_t bd = sB + row * 128 + ((uint32_t)(ch ^ (row & 7)) << 4);
                    asm volatile(
                        "ldmatrix.sync.aligned.m8n8.x4.shared.b16 {%0,%1,%2,%3}, [%4];"
                        : "=r"(rb[2*p][0]), "=r"(rb[2*p][1]),
                          "=r"(rb[2*p+1][0]), "=r"(rb[2*p+1][1])
                        : "r"(bd));
                }
            };
            auto mmas = [&]() {
#pragma unroll
                for (int mi = 0; mi < 4; mi++)
#pragma unroll
                    for (int ni = 0; ni < 4; ni++)
                        asm volatile(
                            "mma.sync.aligned.m16n8k16.row.col.f32.f16.f16.f32 "
                            "{%0,%1,%2,%3}, {%4,%5,%6,%7}, {%8,%9}, {%0,%1,%2,%3};"
                            : "+f"(acc[mi][ni][0]), "+f"(acc[mi][ni][1]),
                              "+f"(acc[mi][ni][2]), "+f"(acc[mi][ni][3])
                            : "r"(ra[mi][0]), "r"(ra[mi][1]),
                              "r"(ra[mi][2]), "r"(ra[mi][3]),
                              "r"(rb[ni][0]), "r"(rb[ni][1]));
            };

            // kk=0 first, hide next-chunk cp.async issue behind its MMAs
            frags(0);
            mmas();
            int nk = kt + STAGES - 1;
            if (nk < ktiles)
                load_tiles<MODE>(smem_u32, nk % STAGES, gA, gB, m0, n0, N, Ks,
                                 koff + nk, tid);
            asm volatile("cp.async.commit_group;");
#pragma unroll
            for (int kk = 16; kk < BKK; kk += 16) { frags(kk); mmas(); }
        }
        asm volatile("cp.async.wait_group 0;");
        __syncthreads();
    }

    if (MODE == 0) {
        float* C = (float*)Cout;
#pragma unroll
        for (int mi = 0; mi < 4; mi++) {
            int r0 = m0 + wm * 64 + mi * 16 + gid;
#pragma unroll
            for (int ni = 0; ni < 4; ni++) {
                int c0 = n0 + wn * 32 + ni * 8 + tig * 2;
                float2 v0 = make_float2(acc[mi][ni][0] * INV_GEMM,
                                        acc[mi][ni][1] * INV_GEMM);
                float2 v1 = make_float2(acc[mi][ni][2] * INV_GEMM,
                                        acc[mi][ni][3] * INV_GEMM);
                *reinterpret_cast<float2*>(C + (size_t)r0 * N + c0) = v0;
                *reinterpret_cast<float2*>(C + (size_t)(r0 + 8) * N + c0) = v1;
            }
        }
    } else if (MODE == 2) {
        float* C = (float*)Cout + (size_t)blockIdx.z * MTOK * RK;
#pragma unroll
        for (int mi = 0; mi < 4; mi++) {
            int r0 = m0 + wm * 64 + mi * 16 + gid;
#pragma unroll
            for (int ni = 0; ni < 4; ni++) {
                int c0 = wn * 32 + ni * 8 + tig * 2;
                if (c0 < RK) {
                    float2 v0 = make_float2(acc[mi][ni][0], acc[mi][ni][1]);
                    float2 v1 = make_float2(acc[mi][ni][2], acc[mi][ni][3]);
                    *reinterpret_cast<float2*>(C + (size_t)r0 * RK + c0) = v0;
                    *reinterpret_cast<float2*>(C + (size_t)(r0 + 8) * RK + c0) = v1;
                }
            }
        }
    } else {
        // MODE 1: acc pair (c0,c1) = (gate,up) raw; local d = wn*16+ni*4+tig
        float* hs = reinterpret_cast<float*>(smem);   // [128][68] padded
#pragma unroll
        for (int mi = 0; mi < 4; mi++) {
            int rl = wm * 64 + mi * 16 + gid;
#pragma unroll
            for (int ni = 0; ni < 4; ni++) {
                int dl = wn * 16 + ni * 4 + tig;
                float g0 = acc[mi][ni][0] * INV_GEMM, u0 = acc[mi][ni][1] * INV_GEMM;
                hs[rl * 68 + dl]       = u0 * g0 / (1.0f + __expf(-g0));
                float g1 = acc[mi][ni][2] * INV_GEMM, u1 = acc[mi][ni][3] * INV_GEMM;
                hs[(rl + 8) * 68 + dl] = u1 * g1 / (1.0f + __expf(-g1));
            }
        }
        __syncthreads();
        __half* He = (__half*)Cout;
#pragma unroll
        for (int it = 0; it < 4; it++) {
            int rl  = it * 32 + (tid >> 3);
            int blk = tid & 7;
            float4 v0 = *reinterpret_cast<float4*>(&hs[rl * 68 + blk * 8]);
            float4 v1 = *reinterpret_cast<float4*>(&hs[rl * 68 + blk * 8 + 4]);
            float x[8] = {v0.x, v0.y, v0.z, v0.w, v1.x, v1.y, v1.z, v1.w};
            __half ob[8];
#pragma unroll
            for (int k = 0; k < 8; k++)
                ob[k] = __float2half_rn(x[k] * 16.0f);    // A-side scale, plain
            *reinterpret_cast<uint4*>(
                He + (size_t)(m0 + rl) * K2P + (n0 + blk * 8)) =
                *reinterpret_cast<const uint4*>(ob);
        }
    }
}

// ---------------- launcher ---------------------------------------------------
extern "C" void kernel_launch(void* const* d_in, const int* in_sizes, int n_in,
                              void* d_out, int out_size) {
    const float* X   = (const float*)d_in[0];
    const float* Wgu = (const float*)d_in[1];
    const float* Agu = (const float*)d_in[2];
    const float* Bgu = (const float*)d_in[3];
    const float* Wd  = (const float*)d_in[4];
    const float* Ad  = (const float*)d_in[5];
    const float* Bd  = (const float*)d_in[6];
    float* out = (float*)d_out;

    __half *Xe, *Wgue, *Ague, *Bgue, *Wde, *Ade, *Bde, *T1e, *T2e, *He;
    float *Pk;
    cudaGetSymbolAddress((void**)&Xe,   g_Xe);
    cudaGetSymbolAddress((void**)&Wgue, g_Wgue);
    cudaGetSymbolAddress((void**)&Ague, g_Ague);
    cudaGetSymbolAddress((void**)&Bgue, g_Bgue);
    cudaGetSymbolAddress((void**)&Wde,  g_Wde);
    cudaGetSymbolAddress((void**)&Ade,  g_Ade);
    cudaGetSymbolAddress((void**)&Bde,  g_Bde);
    cudaGetSymbolAddress((void**)&Pk,   g_Pk);
    cudaGetSymbolAddress((void**)&T1e,  g_T1e);
    cudaGetSymbolAddress((void**)&T2e,  g_T2e);
    cudaGetSymbolAddress((void**)&He,   g_He);

    cudaFuncSetAttribute(gemm_fp16<0>,
                         cudaFuncAttributeMaxDynamicSharedMemorySize, SMEM_BYTES);
    cudaFuncSetAttribute(gemm_fp16<1>,
                         cudaFuncAttributeMaxDynamicSharedMemorySize, SMEM_BYTES);
    cudaFuncSetAttribute(gemm_fp16<2>,
                         cudaFuncAttributeMaxDynamicSharedMemorySize, SMEM_BYTES);

    const int T = 256;
    auto g8 = [&](size_t n) { return (unsigned)((n / 8 + T - 1) / T); };

    // GEMM1 operands (A split, B dup), scales A=16, B=64
    { size_t n = (size_t)MTOK * HID;
      cvt_expand8<true ><<<g8(n), T>>>(X, Xe, n/8, 16.0f); }
    { size_t n = (size_t)2 * DEX * HID;
      cvt_expand8<false><<<g8(n), T>>>(Wgu, Wgue, n/8, 64.0f); }
    { size_t n = (size_t)RK * HID;
      cvt_expand8<false><<<g8(n), T>>>(Agu, Ague, n/8, 64.0f); }
    { size_t n = (size_t)2 * DEX * RK;
      cvt_expand8<false><<<g8(n), T>>>(Bgu, Bgue, n/8, 64.0f); }
    // GEMM2 operands plain fp16, scale 64
    { size_t n = (size_t)HID * DEX;
      cvt_plain8<<<g8(n), T>>>(Wd, Wde, n/8, 64.0f); }
    { size_t n = (size_t)RK * DEX;
      cvt_plain8<<<g8(n), T>>>(Ad, Ade, n/8, 64.0f); }
    { size_t n = (size_t)HID * RK;
      cvt_expand8<false><<<g8(n), T>>>(Bd, Bde, n/8, 64.0f); }

    dim3 blk(NTH);
    const unsigned gr = (unsigned)(((size_t)MTOK * RK + T - 1) / T);

    // T1 raw = 1024*(X @ Agu^T), splitK x4 -> reduce(/256) -> T1e pairs
    gemm_fp16<2><<<dim3(1, MTOK/BM, SPLITK), blk, SMEM_BYTES>>>(
        Xe, Ague, nullptr, nullptr, Pk, RK, K1E, 0);
    reduce_expand<<<gr, T>>>(Pk, T1e);

    // He = 16*swiglu(X@Wgu^T + 0.25*T1@Bgu^T), plain fp16
    gemm_fp16<1><<<dim3(DEX/64, MTOK/BM), blk, SMEM_BYTES>>>(
        Xe, Wgue, T1e, Bgue, He, 2*DEX, K1E, KRE);

    // T2 raw = 1024*(H @ Ad^T), plain x plain, splitK x4 -> reduce -> T2e
    gemm_fp16<2><<<dim3(1, MTOK/BM, SPLITK), blk, SMEM_BYTES>>>(
        He, Ade, nullptr, nullptr, Pk, RK, K2P, 0);
    reduce_expand<<<gr, T>>>(Pk, T2e);

    // out = H@Wd^T + 0.25*T2@Bd^T (plain main segment + expanded tail)
    gemm_fp16<0><<<dim3(HID/BN, MTOK/BM), blk, SMEM_BYTES>>>(
        He, Wde, T2e, Bde, out, HID, K2P, KRE);
}

// round 10
// speedup vs baseline: 2.7968x; 1.5525x over previous
#include <cuda_runtime.h>
#include <cuda_fp16.h>
#include <cstdint>

#define MTOK 8192
#define HID  2048
#define DEX  4096
#define RK   64
#define K1P  HID       // 2048  GEMM1 K (plain fp16 both sides)
#define K2P  DEX       // 4096  GEMM2 K (plain fp16 both sides)
#define KRE  (2*RK)    // 128   LoRA tail K (split pairs)
#define SPLITK 4
// scaling: A-side stored = 16*true, B-side = 64*true, GEMM raw = 1024*true
#define INV_GEMM (1.0f/1024.0f)

// ---------------- scratch (device globals) ----------------------------------
__device__ __align__(16) __half g_Xe  [(size_t)MTOK * K1P];
__device__ __align__(16) __half g_Wgue[(size_t)2*DEX * K1P];
__device__ __align__(16) __half g_Ague[(size_t)RK * K1P];
__device__ __align__(16) __half g_Bgue[(size_t)2*DEX * KRE];
__device__ __align__(16) __half g_Wde [(size_t)HID * K2P];
__device__ __align__(16) __half g_Ade [(size_t)RK * K2P];
__device__ __align__(16) __half g_Bde [(size_t)HID * KRE];
__device__ __align__(16) float  g_Pk  [(size_t)SPLITK * MTOK * RK];
__device__ __align__(16) __half g_T1e [(size_t)MTOK * KRE];
__device__ __align__(16) __half g_T2e [(size_t)MTOK * KRE];
__device__ __align__(16) __half g_He  [(size_t)MTOK * K2P];

// ---------------- fp32 -> fp16 split pair (B-dup) for LoRA tails ------------
template<bool ASIDE>
__global__ void cvt_expand8(const float* __restrict__ in,
                            __half* __restrict__ out,
                            size_t n8, float scale) {
    size_t i = (size_t)blockIdx.x * blockDim.x + threadIdx.x;
    if (i >= n8) return;
    const float4* p = reinterpret_cast<const float4*>(in) + i * 2;
    float4 v0 = p[0], v1 = p[1];
    float x[8] = {v0.x, v0.y, v0.z, v0.w, v1.x, v1.y, v1.z, v1.w};
    __half ob[16];
#pragma unroll
    for (int k = 0; k < 8; k++) {
        float xv = x[k] * scale;
        __half hi = __float2half_rn(xv);
        ob[2*k] = hi;
        if (ASIDE) ob[2*k+1] = __float2half_rn(xv - __half2float(hi));
        else       ob[2*k+1] = hi;
    }
    uint4* o = reinterpret_cast<uint4*>(out + i * 16);
    const uint4* s = reinterpret_cast<const uint4*>(ob);
    o[0] = s[0]; o[1] = s[1];
}

// ---------------- fp32 -> plain fp16 (8 elems/thread) -----------------------
__global__ void cvt_plain8(const float* __restrict__ in,
                           __half* __restrict__ out,
                           size_t n8, float scale) {
    size_t i = (size_t)blockIdx.x * blockDim.x + threadIdx.x;
    if (i >= n8) return;
    const float4* p = reinterpret_cast<const float4*>(in) + i * 2;
    float4 v0 = p[0], v1 = p[1];
    float x[8] = {v0.x, v0.y, v0.z, v0.w, v1.x, v1.y, v1.z, v1.w};
    __half ob[8];
#pragma unroll
    for (int k = 0; k < 8; k++) ob[k] = __float2half_rn(x[k] * scale);
    *reinterpret_cast<uint4*>(out + i * 8) = *reinterpret_cast<const uint4*>(ob);
}

// ---------------- splitK reduce + scale + A-side fp16 pair ------------------
// raw = 1024*true; A-side of 0.25*true*16 => raw/256
__global__ void reduce_expand(const float* __restrict__ P,
                              __half* __restrict__ out) {
    size_t idx = (size_t)blockIdx.x * blockDim.x + threadIdx.x;
    if (idx >= (size_t)MTOK * RK) return;
    const size_t S = (size_t)MTOK * RK;
    float s = (P[idx] + P[idx + S] + P[idx + 2*S] + P[idx + 3*S]) * (1.0f/256.0f);
    __half hi = __float2half_rn(s);
    out[2*idx]   = hi;
    out[2*idx+1] = __float2half_rn(s - __half2float(hi));
}

// ---------------- fp16 TN GEMM (mma.sync) -----------------------------------
// MODE 0: C fp32 (descaled), LoRA K-tail.  MODE 1: fused SwiGLU -> He plain
// fp16 (x16), gate/up interleaved B rows, n0 = d-offset.  MODE 2: splitK raw.
#define BM 128
#define BN 128
#define BKK 64
#define STAGES 3
#define NTH 256
#define TILE_BYTES (BM * BKK * 2)              // 16 KB
#define SMEM_BYTES (2 * STAGES * TILE_BYTES)   // 96 KB -> 2 CTAs/SM

template<int MODE>
__device__ __forceinline__ void load_tiles(uint32_t smem_u32, int stage,
                                           const __half* gA,
                                           const __half* gB,
                                           int m0, int n0, int N, int Ks,
                                           int kt, int tid) {
#pragma unroll
    for (int i = 0; i < 4; i++) {
        int c = tid + i * NTH;
        int row = c >> 3;
        int col = c & 7;
        uint32_t sw = (uint32_t)(col ^ (row & 7)) << 4;
        uint32_t da = smem_u32 + (uint32_t)stage * TILE_BYTES + row * 128 + sw;
        const void* sa = (const void*)(gA + (size_t)(m0 + row) * Ks
                                          + (size_t)kt * BKK + col * 8);
        asm volatile("cp.async.cg.shared.global [%0], [%1], 16;"
                     :: "r"(da), "l"(sa));
        int brow;
        if (MODE == 1) {
            brow = (row & 1) ? (DEX + n0 + (row >> 1)) : (n0 + (row >> 1));
        } else {
            brow = n0 + row; brow = brow < N ? brow : N - 1;  // clamp (N=64)
        }
        uint32_t db = smem_u32 + (uint32_t)(STAGES + stage) * TILE_BYTES
                               + row * 128 + sw;
        const void* sb = (const void*)(gB + (size_t)brow * Ks
                                          + (size_t)kt * BKK + col * 8);
        asm volatile("cp.async.cg.shared.global [%0], [%1], 16;"
                     :: "r"(db), "l"(sb));
    }
}

template<int MODE>
__global__ __launch_bounds__(NTH, 2) void gemm_fp16(
    const __half* __restrict__ A,  const __half* __restrict__ B,
    const __half* __restrict__ A2, const __half* __restrict__ B2,
    void* __restrict__ Cout, int N, int K, int Kt) {
    extern __shared__ char smem[];
    const uint32_t smem_u32 = (uint32_t)__cvta_generic_to_shared(smem);
    const int tid  = threadIdx.x;
    const int warp = tid >> 5, lane = tid & 31;
    const int wm = warp >> 2, wn = warp & 3;
    const int gid = lane >> 2, tig = lane & 3;

    // grouped CTA swizzle (8 y-tiles per x step) for L2 reuse of B panels
    int bx = blockIdx.x, by = blockIdx.y;
    if (MODE != 2 && gridDim.x > 1) {
        const int GRP = 8;
        int lin = by * gridDim.x + bx;
        int per = gridDim.x * GRP;
        int g   = lin / per, rem = lin % per;
        int gy  = g * GRP;
        int h   = gridDim.y - gy; if (h > GRP) h = GRP;
        by = gy + rem % h;
        bx = rem / h;
    }
    const int m0 = by * BM;
    const int n0 = bx * ((MODE == 1) ? 64 : BN);

    float acc[4][4][4];
#pragma unroll
    for (int a = 0; a < 4; a++)
#pragma unroll
        for (int b = 0; b < 4; b++)
#pragma unroll
            for (int c = 0; c < 4; c++) acc[a][b][c] = 0.0f;

    const int a_row_in = (lane & 15);
    const int a_ch_in  = (lane >> 4);
    const int b_row_in = ((lane >> 4) << 3) + (lane & 7);
    const int b_ch_in  = ((lane >> 3) & 1);

    const int cps   = (MODE == 2) ? (K / BKK) / SPLITK : 0;
    const int koff  = (MODE == 2) ? blockIdx.z * cps : 0;
    const int nseg  = (MODE == 2) ? 1 : 2;

    for (int seg = 0; seg < nseg; seg++) {
        const __half* gA = seg ? A2 : A;
        const __half* gB = seg ? B2 : B;
        const int Ks = seg ? Kt : K;
        if (Ks == 0) break;
        const int ktiles = (MODE == 2) ? cps : Ks / BKK;

        for (int p = 0; p < STAGES - 1; p++) {
            if (p < ktiles)
                load_tiles<MODE>(smem_u32, p, gA, gB, m0, n0, N, Ks,
                                 koff + p, tid);
            asm volatile("cp.async.commit_group;");
        }

        for (int kt = 0; kt < ktiles; kt++) {
            asm volatile("cp.async.wait_group %0;" :: "n"(STAGES - 2));
            __syncthreads();

            const int st = kt % STAGES;
            const uint32_t sA = smem_u32 + (uint32_t)st * TILE_BYTES;
            const uint32_t sB = smem_u32 + (uint32_t)(STAGES + st) * TILE_BYTES;

            uint32_t ra[4][4], rb[4][2];
            auto frags = [&](int kk) {
#pragma unroll
                for (int mi = 0; mi < 4; mi++) {
                    int row = wm * 64 + mi * 16 + a_row_in;
                    int ch  = (kk >> 3) + a_ch_in;
                    uint32_t ad = sA + row * 128 + ((uint32_t)(ch ^ (row & 7)) << 4);
                    asm volatile(
                        "ldmatrix.sync.aligned.m8n8.x4.shared.b16 {%0,%1,%2,%3}, [%4];"
                        : "=r"(ra[mi][0]), "=r"(ra[mi][1]),
                          "=r"(ra[mi][2]), "=r"(ra[mi][3])
                        : "r"(ad));
                }
#pragma unroll
                for (int p = 0; p < 2; p++) {
                    int row = wn * 32 + p * 16 + b_row_in;
                    int ch  = (kk >> 3) + b_ch_in;
                    uint32_t bd = sB + row * 128 + ((uint32_t)(ch ^ (row & 7)) << 4);
                    asm volatile(
                        "ldmatrix.sync.aligned.m8n8.x4.shared.b16 {%0,%1,%2,%3}, [%4];"
                        : "=r"(rb[2*p][0]), "=r"(rb[2*p][1]),
                          "=r"(rb[2*p+1][0]), "=r"(rb[2*p+1][1])
                        : "r"(bd));
                }
            };
            auto mmas = [&]() {
#pragma unroll
                for (int mi = 0; mi < 4; mi++)
#pragma unroll
                    for (int ni = 0; ni < 4; ni++)
                        asm volatile(
                            "mma.sync.aligned.m16n8k16.row.col.f32.f16.f16.f32 "
                            "{%0,%1,%2,%3}, {%4,%5,%6,%7}, {%8,%9}, {%0,%1,%2,%3};"
                            : "+f"(acc[mi][ni][0]), "+f"(acc[mi][ni][1]),
                              "+f"(acc[mi][ni][2]), "+f"(acc[mi][ni][3])
                            : "r"(ra[mi][0]), "r"(ra[mi][1]),
                              "r"(ra[mi][2]), "r"(ra[mi][3]),
                              "r"(rb[ni][0]), "r"(rb[ni][1]));
            };

            // kk=0 first, hide next-chunk cp.async issue behind its MMAs
            frags(0);
            mmas();
            int nk = kt + STAGES - 1;
            if (nk < ktiles)
                load_tiles<MODE>(smem_u32, nk % STAGES, gA, gB, m0, n0, N, Ks,
                                 koff + nk, tid);
            asm volatile("cp.async.commit_group;");
#pragma unroll
            for (int kk = 16; kk < BKK; kk += 16) { frags(kk); mmas(); }
        }
        asm volatile("cp.async.wait_group 0;");
        __syncthreads();
    }

    if (MODE == 0) {
        float* C = (float*)Cout;
#pragma unroll
        for (int mi = 0; mi < 4; mi++) {
            int r0 = m0 + wm * 64 + mi * 16 + gid;
#pragma unroll
            for (int ni = 0; ni < 4; ni++) {
                int c0 = n0 + wn * 32 + ni * 8 + tig * 2;
                float2 v0 = make_float2(acc[mi][ni][0] * INV_GEMM,
                                        acc[mi][ni][1] * INV_GEMM);
                float2 v1 = make_float2(acc[mi][ni][2] * INV_GEMM,
                                        acc[mi][ni][3] * INV_GEMM);
                *reinterpret_cast<float2*>(C + (size_t)r0 * N + c0) = v0;
                *reinterpret_cast<float2*>(C + (size_t)(r0 + 8) * N + c0) = v1;
            }
        }
    } else if (MODE == 2) {
        float* C = (float*)Cout + (size_t)blockIdx.z * MTOK * RK;
#pragma unroll
        for (int mi = 0; mi < 4; mi++) {
            int r0 = m0 + wm * 64 + mi * 16 + gid;
#pragma unroll
            for (int ni = 0; ni < 4; ni++) {
                int c0 = wn * 32 + ni * 8 + tig * 2;
                if (c0 < RK) {
                    float2 v0 = make_float2(acc[mi][ni][0], acc[mi][ni][1]);
                    float2 v1 = make_float2(acc[mi][ni][2], acc[mi][ni][3]);
                    *reinterpret_cast<float2*>(C + (size_t)r0 * RK + c0) = v0;
                    *reinterpret_cast<float2*>(C + (size_t)(r0 + 8) * RK + c0) = v1;
                }
            }
        }
    } else {
        // MODE 1: acc pair (c0,c1) = (gate,up) raw; local d = wn*16+ni*4+tig
        float* hs = reinterpret_cast<float*>(smem);   // [128][68] padded
#pragma unroll
        for (int mi = 0; mi < 4; mi++) {
            int rl = wm * 64 + mi * 16 + gid;
#pragma unroll
            for (int ni = 0; ni < 4; ni++) {
                int dl = wn * 16 + ni * 4 + tig;
                float g0 = acc[mi][ni][0] * INV_GEMM, u0 = acc[mi][ni][1] * INV_GEMM;
                hs[rl * 68 + dl]       = u0 * g0 / (1.0f + __expf(-g0));
                float g1 = acc[mi][ni][2] * INV_GEMM, u1 = acc[mi][ni][3] * INV_GEMM;
                hs[(rl + 8) * 68 + dl] = u1 * g1 / (1.0f + __expf(-g1));
            }
        }
        __syncthreads();
        __half* He = (__half*)Cout;
#pragma unroll
        for (int it = 0; it < 4; it++) {
            int rl  = it * 32 + (tid >> 3);
            int blk = tid & 7;
            float4 v0 = *reinterpret_cast<float4*>(&hs[rl * 68 + blk * 8]);
            float4 v1 = *reinterpret_cast<float4*>(&hs[rl * 68 + blk * 8 + 4]);
            float x[8] = {v0.x, v0.y, v0.z, v0.w, v1.x, v1.y, v1.z, v1.w};
            __half ob[8];
#pragma unroll
            for (int k = 0; k < 8; k++)
                ob[k] = __float2half_rn(x[k] * 16.0f);    // A-side scale, plain
            *reinterpret_cast<uint4*>(
                He + (size_t)(m0 + rl) * K2P + (n0 + blk * 8)) =
                *reinterpret_cast<const uint4*>(ob);
        }
    }
}

// ---------------- launcher ---------------------------------------------------
extern "C" void kernel_launch(void* const* d_in, const int* in_sizes, int n_in,
                              void* d_out, int out_size) {
    const float* X   = (const float*)d_in[0];
    const float* Wgu = (const float*)d_in[1];
    const float* Agu = (const float*)d_in[2];
    const float* Bgu = (const float*)d_in[3];
    const float* Wd  = (const float*)d_in[4];
    const float* Ad  = (const float*)d_in[5];
    const float* Bd  = (const float*)d_in[6];
    float* out = (float*)d_out;

    __half *Xe, *Wgue, *Ague, *Bgue, *Wde, *Ade, *Bde, *T1e, *T2e, *He;
    float *Pk;
    cudaGetSymbolAddress((void**)&Xe,   g_Xe);
    cudaGetSymbolAddress((void**)&Wgue, g_Wgue);
    cudaGetSymbolAddress((void**)&Ague, g_Ague);
    cudaGetSymbolAddress((void**)&Bgue, g_Bgue);
    cudaGetSymbolAddress((void**)&Wde,  g_Wde);
    cudaGetSymbolAddress((void**)&Ade,  g_Ade);
    cudaGetSymbolAddress((void**)&Bde,  g_Bde);
    cudaGetSymbolAddress((void**)&Pk,   g_Pk);
    cudaGetSymbolAddress((void**)&T1e,  g_T1e);
    cudaGetSymbolAddress((void**)&T2e,  g_T2e);
    cudaGetSymbolAddress((void**)&He,   g_He);

    cudaFuncSetAttribute(gemm_fp16<0>,
                         cudaFuncAttributeMaxDynamicSharedMemorySize, SMEM_BYTES);
    cudaFuncSetAttribute(gemm_fp16<1>,
                         cudaFuncAttributeMaxDynamicSharedMemorySize, SMEM_BYTES);
    cudaFuncSetAttribute(gemm_fp16<2>,
                         cudaFuncAttributeMaxDynamicSharedMemorySize, SMEM_BYTES);

    const int T = 256;
    auto g8 = [&](size_t n) { return (unsigned)((n / 8 + T - 1) / T); };

    // all big operands plain fp16: A-side scale 16, B-side scale 64
    { size_t n = (size_t)MTOK * HID;
      cvt_plain8<<<g8(n), T>>>(X, Xe, n/8, 16.0f); }
    { size_t n = (size_t)2 * DEX * HID;
      cvt_plain8<<<g8(n), T>>>(Wgu, Wgue, n/8, 64.0f); }
    { size_t n = (size_t)RK * HID;
      cvt_plain8<<<g8(n), T>>>(Agu, Ague, n/8, 64.0f); }
    { size_t n = (size_t)HID * DEX;
      cvt_plain8<<<g8(n), T>>>(Wd, Wde, n/8, 64.0f); }
    { size_t n = (size_t)RK * DEX;
      cvt_plain8<<<g8(n), T>>>(Ad, Ade, n/8, 64.0f); }
    // LoRA B tails keep split-pair expansion (B-dup form)
    { size_t n = (size_t)2 * DEX * RK;
      cvt_expand8<false><<<g8(n), T>>>(Bgu, Bgue, n/8, 64.0f); }
    { size_t n = (size_t)HID * RK;
      cvt_expand8<false><<<g8(n), T>>>(Bd, Bde, n/8, 64.0f); }

    dim3 blk(NTH);
    const unsigned gr = (unsigned)(((size_t)MTOK * RK + T - 1) / T);

    // T1 raw = 1024*(X @ Agu^T), splitK x4 -> reduce(/256) -> T1e pairs
    gemm_fp16<2><<<dim3(1, MTOK/BM, SPLITK), blk, SMEM_BYTES>>>(
        Xe, Ague, nullptr, nullptr, Pk, RK, K1P, 0);
    reduce_expand<<<gr, T>>>(Pk, T1e);

    // He = 16*swiglu(X@Wgu^T + 0.25*T1@Bgu^T), plain fp16
    gemm_fp16<1><<<dim3(DEX/64, MTOK/BM), blk, SMEM_BYTES>>>(
        Xe, Wgue, T1e, Bgue, He, 2*DEX, K1P, KRE);

    // T2 raw = 1024*(H @ Ad^T), splitK x4 -> reduce -> T2e
    gemm_fp16<2><<<dim3(1, MTOK/BM, SPLITK), blk, SMEM_BYTES>>>(
        He, Ade, nullptr, nullptr, Pk, RK, K2P, 0);
    reduce_expand<<<gr, T>>>(Pk, T2e);

    // out = H@Wd^T + 0.25*T2@Bd^T (plain main segment + split-pair tail)
    gemm_fp16<0><<<dim3(HID/BN, MTOK/BM), blk, SMEM_BYTES>>>(
        He, Wde, T2e, Bde, out, HID, K2P, KRE);
}